// round 6
// baseline (speedup 1.0000x reference)
#include <cuda_runtime.h>
#include <cuda_bf16.h>
#include <cstdint>

#define Bsz 64
#define Tsz 512
#define Isz 512
#define Hsz 512

// ---------------------------------------------------------------------------
// Static device scratch
// ---------------------------------------------------------------------------
__device__ float g_xproj[2u * Tsz * Bsz * Hsz];   // [d][t][b][h]

// ---------------------------------------------------------------------------
// Packed fp32x2 helpers (Blackwell FFMA2 path)
// ---------------------------------------------------------------------------
typedef unsigned long long ull;

__device__ __forceinline__ ull ffma2(ull a, ull b, ull c) {
    ull d;
    asm("fma.rn.f32x2 %0, %1, %2, %3;" : "=l"(d) : "l"(a), "l"(b), "l"(c));
    return d;
}
__device__ __forceinline__ ull pack2(float x) {
    ull d;
    asm("mov.b64 %0, {%1, %1};" : "=l"(d) : "f"(x));
    return d;
}
__device__ __forceinline__ ull pack2f(float x, float y) {
    ull d;
    asm("mov.b64 %0, {%1, %2};" : "=l"(d) : "f"(x), "f"(y));
    return d;
}
__device__ __forceinline__ float2 unpack2(ull a) {
    float2 r;
    asm("mov.b64 {%0, %1}, %2;" : "=f"(r.x), "=f"(r.y) : "l"(a));
    return r;
}

// ---------------------------------------------------------------------------
// Cluster / mbarrier helpers
// ---------------------------------------------------------------------------
__device__ __forceinline__ uint32_t smem_u32(const void* p) {
    uint32_t a;
    asm("{ .reg .u64 t; cvta.to.shared.u64 t, %1; cvt.u32.u64 %0, t; }"
        : "=r"(a) : "l"(p));
    return a;
}
__device__ __forceinline__ void mbar_init(uint32_t addr, uint32_t cnt) {
    asm volatile("mbarrier.init.shared.b64 [%0], %1;" :: "r"(addr), "r"(cnt) : "memory");
}
__device__ __forceinline__ uint32_t mapa_rank(uint32_t local, uint32_t rank) {
    uint32_t r;
    asm("mapa.shared::cluster.u32 %0, %1, %2;" : "=r"(r) : "r"(local), "r"(rank));
    return r;
}
__device__ __forceinline__ void st_cluster_b64(uint32_t addr, ull v) {
    asm volatile("st.shared::cluster.b64 [%0], %1;" :: "r"(addr), "l"(v) : "memory");
}
__device__ __forceinline__ void mbar_arrive_cluster(uint32_t remote_addr) {
    asm volatile("mbarrier.arrive.release.cluster.shared::cluster.b64 _, [%0];"
                 :: "r"(remote_addr) : "memory");
}
__device__ __forceinline__ void mbar_wait_acq_cluster(uint32_t addr, uint32_t parity) {
    asm volatile(
        "{\n\t"
        ".reg .pred P;\n\t"
        "WAIT_%=:\n\t"
        "mbarrier.try_wait.parity.acquire.cluster.shared::cta.b64 P, [%0], %1, 0x989680;\n\t"
        "@!P bra WAIT_%=;\n\t"
        "}" :: "r"(addr), "r"(parity) : "memory");
}
__device__ __forceinline__ void cluster_sync_() {
    asm volatile("barrier.cluster.arrive.aligned;" ::: "memory");
    asm volatile("barrier.cluster.wait.aligned;" ::: "memory");
}

// ---------------------------------------------------------------------------
// Phase 1: xproj = x @ Wx^T + b.  (unchanged from round 4 — known good)
// ---------------------------------------------------------------------------
__global__ void __launch_bounds__(256, 2) xproj_gemm_kernel(
    const float* __restrict__ x,
    const float* __restrict__ Wf, const float* __restrict__ bf,
    const float* __restrict__ Wb, const float* __restrict__ bb)
{
    const int d = blockIdx.z;
    const float* __restrict__ W    = d ? Wb : Wf;
    const float* __restrict__ bias = d ? bb : bf;

    const int mt = blockIdx.y << 7;
    const int b  = mt >> 9;
    const int t0 = mt & 511;
    const int n0 = blockIdx.x << 7;

    __shared__ float sA[8][132];
    __shared__ float sB[8][132];

    const int tid = threadIdx.x;
    const int r  = tid >> 1;
    const int cc = (tid & 1) * 4;

    const float* ap = x + ((size_t)(b * Tsz + t0 + r)) * Isz + cc;
    const float* bp = W + ((size_t)(n0 + r)) * Isz + cc;

    float4 ra = *(const float4*)ap;
    float4 rb = *(const float4*)bp;

    const int tr = tid >> 4;
    const int tc = tid & 15;

    ull acc2[8][4];
#pragma unroll
    for (int i = 0; i < 8; i++)
#pragma unroll
        for (int j = 0; j < 4; j++) acc2[i][j] = 0ull;

    for (int k0 = 0; k0 < Isz; k0 += 8) {
        __syncthreads();
        sA[cc + 0][r] = ra.x; sA[cc + 1][r] = ra.y;
        sA[cc + 2][r] = ra.z; sA[cc + 3][r] = ra.w;
        sB[cc + 0][r] = rb.x; sB[cc + 1][r] = rb.y;
        sB[cc + 2][r] = rb.z; sB[cc + 3][r] = rb.w;
        __syncthreads();

        if (k0 + 8 < Isz) {
            ra = *(const float4*)(ap + k0 + 8);
            rb = *(const float4*)(bp + k0 + 8);
        }

#pragma unroll
        for (int k = 0; k < 8; k++) {
            float4 a0 = *(const float4*)&sA[k][tr * 4];
            float4 a1 = *(const float4*)&sA[k][64 + tr * 4];
            ulonglong2 b0q = *(const ulonglong2*)&sB[k][tc * 4];
            ulonglong2 b1q = *(const ulonglong2*)&sB[k][64 + tc * 4];
            float am[8] = {a0.x, a0.y, a0.z, a0.w, a1.x, a1.y, a1.z, a1.w};
#pragma unroll
            for (int i = 0; i < 8; i++) {
                ull apk = pack2(am[i]);
                acc2[i][0] = ffma2(apk, b0q.x, acc2[i][0]);
                acc2[i][1] = ffma2(apk, b0q.y, acc2[i][1]);
                acc2[i][2] = ffma2(apk, b1q.x, acc2[i][2]);
                acc2[i][3] = ffma2(apk, b1q.y, acc2[i][3]);
            }
        }
    }

    float4 bias0 = *(const float4*)(bias + n0 + tc * 4);
    float4 bias1 = *(const float4*)(bias + n0 + 64 + tc * 4);

#pragma unroll
    for (int mi = 0; mi < 8; mi++) {
        int rloc = (mi < 4) ? (tr * 4 + mi) : (64 + tr * 4 + (mi - 4));
        int t = t0 + rloc;
        float* op = g_xproj + (((size_t)d * Tsz + t) * Bsz + b) * Hsz + n0;
        float2 p0 = unpack2(acc2[mi][0]);
        float2 p1 = unpack2(acc2[mi][1]);
        float2 p2 = unpack2(acc2[mi][2]);
        float2 p3 = unpack2(acc2[mi][3]);
        float4 o0, o1;
        o0.x = p0.x + bias0.x; o0.y = p0.y + bias0.y;
        o0.z = p1.x + bias0.z; o0.w = p1.y + bias0.w;
        o1.x = p2.x + bias1.x; o1.y = p2.y + bias1.y;
        o1.z = p3.x + bias1.z; o1.w = p3.y + bias1.w;
        *(float4*)(op + tc * 4)      = o0;
        *(float4*)(op + 64 + tc * 4) = o1;
    }
}

// ---------------------------------------------------------------------------
// Phase 2: persistent scan with 8-CTA clusters + DSMEM h-exchange.
// 128 CTAs = (2 dir) x (8 btile) x (8 ctile); cluster = the 8 ctiles of one
// (dir,btile); cluster rank == ctile. CTA owns 8 batches x 64 cols.
// Per step: compute from local HS[parity], tanh, STG y (streaming, never
// re-read), push the 2 result floats into HS[!parity] of all 8 cluster CTAs
// via st.shared::cluster, then release-arrive on all 8 mbarriers.
//
// smem (floats):
//   [0..16)  2 mbarriers (8B each) + pad
//   WS[kc][k'][c]  kc<32, k'<16, c<64   chunk stride 1028
//   HS0/HS1[kc][b][kk] kc<32, b<8, kk<16  chunk stride 132
// ---------------------------------------------------------------------------
#define SCAN_CTAS 128
#define WCH 1028
#define HCH 132
#define HS_FLOATS (32 * HCH)

__global__ void __launch_bounds__(256) __cluster_dims__(8, 1, 1) scan_kernel(
    const float* __restrict__ h0f, const float* __restrict__ h0b,
    const float* __restrict__ Whf, const float* __restrict__ Whb,
    float* __restrict__ y)
{
    extern __shared__ float sm[];
    float* WS  = sm + 16;
    float* HSb[2];
    HSb[0] = WS + 32 * WCH;
    HSb[1] = HSb[0] + HS_FLOATS;

    const uint32_t sbase = smem_u32(sm);
    const uint32_t mb0 = sbase;
    const uint32_t mb1 = sbase + 8;
    const uint32_t hs0_a = sbase + (16 + 32 * WCH) * 4;
    const uint32_t hs1_a = hs0_a + HS_FLOATS * 4;

    const int cta   = blockIdx.x;
    const int dir   = cta >> 6;
    const int btile = (cta >> 3) & 7;
    const int b0    = btile << 3;
    const int cbase = (cta & 7) << 6;

    const float* __restrict__ Wh = dir ? Whb : Whf;
    const float* __restrict__ h0 = dir ? h0b : h0f;

    const int tid = threadIdx.x;

    if (tid == 0) { mbar_init(mb0, 8); mbar_init(mb1, 8); }

    // ---- load W slice once, chunked k-major ----
    for (int i = tid; i < 64 * 128; i += 256) {
        int c  = i >> 7;
        int k4 = (i & 127) * 4;
        float4 v = *(const float4*)(Wh + (size_t)(cbase + c) * Hsz + k4);
        int kc = k4 >> 4, kk = k4 & 15;
        float* wsl = WS + kc * WCH + kk * 64 + c;
        wsl[0 * 64] = v.x; wsl[1 * 64] = v.y; wsl[2 * 64] = v.z; wsl[3 * 64] = v.w;
    }

    // ---- stage h0 into HS0 (local) ----
    for (int i = tid; i < 1024; i += 256) {
        int b = i >> 7;
        int k = (i & 127) * 4;
        float4 v = *(const float4*)(h0 + (size_t)(b0 + b) * Hsz + k);
        int kcx = k >> 4, kk = k & 15;
        *(float4*)&HSb[0][kcx * HCH + b * 16 + kk] = v;
    }
    __syncthreads();
    cluster_sync_();   // mbarriers + HS0 visible cluster-wide before any arrive

    const int lane = tid & 31;
    const int w    = tid >> 5;
    const int kc   = lane;
    const int c0   = w << 3;

    // outputs of this lane after the halving butterfly (o = b_local*8 + c_local)
    const int o0 = ((lane & 1) << 5) | (((lane >> 1) & 1) << 4) |
                   (((lane >> 2) & 1) << 3) | (((lane >> 3) & 1) << 2) |
                   (((lane >> 4) & 1) << 1);
    const int bl    = o0 >> 3;               // local batch 0..7
    const int b_out = b0 + bl;
    const int colg  = cbase + c0 + (o0 & 7); // global col (even), and colg+1

    // precomputed DSMEM destination addresses for this lane's result slot
    const uint32_t slot = (uint32_t)(((colg >> 4) * HCH + bl * 16 + (colg & 15)) * 4);
    uint32_t dstA[2][8];
#pragma unroll
    for (int rk = 0; rk < 8; rk++) {
        dstA[0][rk] = mapa_rank(hs0_a + slot, rk);
        dstA[1][rk] = mapa_rank(hs1_a + slot, rk);
    }

    int ph0 = 0, ph1 = 0;

    for (int step = 0; step < Tsz; step++) {
        const int t = dir ? (Tsz - 1 - step) : step;

        // xproj for this lane's outputs (barrier-independent, issue early)
        const float2 xp = __ldcg((const float2*)(
            g_xproj + (((size_t)dir * Tsz + t) * Bsz + b_out) * Hsz + colg));

        if (step > 0) {
            if (step & 1) { mbar_wait_acq_cluster(mb1, ph1); ph1 ^= 1; }
            else          { mbar_wait_acq_cluster(mb0, ph0); ph0 ^= 1; }
        }

        const float* HS = HSb[step & 1];
        const float* hp = HS + kc * HCH;
        const float* wp = WS + kc * WCH + c0;

        // ---- 8b x 8c f32x2 tile over this lane's K-chunk of 16 ----
        ull acc[8][4];
#pragma unroll
        for (int b = 0; b < 8; b++)
#pragma unroll
            for (int j = 0; j < 4; j++) acc[b][j] = 0ull;

#pragma unroll
        for (int kk4 = 0; kk4 < 16; kk4 += 4) {
            float4 hv[8];
#pragma unroll
            for (int b = 0; b < 8; b++)
                hv[b] = *(const float4*)(hp + b * 16 + kk4);
#pragma unroll
            for (int k2 = 0; k2 < 4; k2++) {
                const float* wrow = wp + (kk4 + k2) * 64;
                ulonglong2 wa = *(const ulonglong2*)(wrow);
                ulonglong2 wb = *(const ulonglong2*)(wrow + 4);
#pragma unroll
                for (int b = 0; b < 8; b++) {
                    float hs = (k2 == 0) ? hv[b].x : (k2 == 1) ? hv[b].y
                             : (k2 == 2) ? hv[b].z : hv[b].w;
                    ull hpk = pack2(hs);
                    acc[b][0] = ffma2(hpk, wa.x, acc[b][0]);
                    acc[b][1] = ffma2(hpk, wa.y, acc[b][1]);
                    acc[b][2] = ffma2(hpk, wb.x, acc[b][2]);
                    acc[b][3] = ffma2(hpk, wb.y, acc[b][3]);
                }
            }
        }

        // ---- unpack to 64 scalars (o = b*8 + c) ----
        float v[64];
#pragma unroll
        for (int b = 0; b < 8; b++)
#pragma unroll
            for (int cp = 0; cp < 4; cp++) {
                float2 u = unpack2(acc[b][cp]);
                v[b * 8 + cp * 2]     = u.x;
                v[b * 8 + cp * 2 + 1] = u.y;
            }

        // ---- 5-level jammed halving butterfly over the 32 kc lanes ----
        int n = 64;
#pragma unroll
        for (int m = 1; m < 32; m <<= 1) {
            n >>= 1;
            const bool hi = (lane & m) != 0;
#pragma unroll
            for (int i = 0; i < n; i++) {
                float send = hi ? v[i] : v[i + n];
                float keep = hi ? v[i + n] : v[i];
                v[i] = keep + __shfl_xor_sync(0xffffffffu, send, m);
            }
        }

        float r0 = tanhf(v[0] + xp.x);
        float r1 = tanhf(v[1] + xp.y);

        // streaming store of y (never re-read by the scan)
        float* yp = y + ((size_t)b_out * Tsz + t) * (2 * Hsz) + (dir << 9) + colg;
        __stcg((float2*)yp, make_float2(r0, r1));

        if (step < Tsz - 1) {
            // ---- DSMEM push: result into HS[!parity] of all 8 cluster CTAs ----
            const ull pr = pack2f(r0, r1);
            const int wbuf = (step & 1) ^ 1;
#pragma unroll
            for (int rk = 0; rk < 8; rk++)
                st_cluster_b64(dstA[wbuf][rk], pr);

            __syncthreads();   // all lanes' pushes done before signaling

            if (tid < 8) {
                uint32_t peer_mb = mapa_rank(((step + 1) & 1) ? mb1 : mb0, tid);
                mbar_arrive_cluster(peer_mb);
            }
        }
    }

    cluster_sync_();   // no CTA exits while peers' DSMEM traffic may be in flight
}

// ---------------------------------------------------------------------------
// Tail: hT_f = hs_f[T-1], hT_b = hs_b[t=0]
// ---------------------------------------------------------------------------
__global__ void tail_kernel(float* __restrict__ out)
{
    const int b = blockIdx.x;
    const int k = threadIdx.x;
    const float* y = out;
    const size_t yN = (size_t)Bsz * Tsz * 2 * Hsz;
    out[yN + (size_t)b * Hsz + k] =
        y[((size_t)b * Tsz + (Tsz - 1)) * (2 * Hsz) + k];
    out[yN + (size_t)Bsz * Hsz + (size_t)b * Hsz + k] =
        y[((size_t)b * Tsz) * (2 * Hsz) + Hsz + k];
}

// ---------------------------------------------------------------------------
extern "C" void kernel_launch(void* const* d_in, const int* in_sizes, int n_in,
                              void* d_out, int out_size)
{
    const float* x     = (const float*)d_in[0];
    const float* h0f   = (const float*)d_in[1];
    const float* h0b   = (const float*)d_in[2];
    const float* Wxf_w = (const float*)d_in[3];
    const float* Wxf_b = (const float*)d_in[4];
    const float* Whf_w = (const float*)d_in[5];
    const float* Wxb_w = (const float*)d_in[6];
    const float* Wxb_b = (const float*)d_in[7];
    const float* Whb_w = (const float*)d_in[8];
    float* out = (float*)d_out;

    const int scan_smem = (16 + 32 * WCH + 2 * HS_FLOATS) * (int)sizeof(float);
    cudaFuncSetAttribute(scan_kernel,
                         cudaFuncAttributeMaxDynamicSharedMemorySize, scan_smem);

    dim3 ggrid(4, 256, 2);
    xproj_gemm_kernel<<<ggrid, 256>>>(x, Wxf_w, Wxf_b, Wxb_w, Wxb_b);

    scan_kernel<<<SCAN_CTAS, 256, scan_smem>>>(h0f, h0b, Whf_w, Whb_w, out);

    tail_kernel<<<Bsz, Hsz>>>(out);
}

// round 7
// speedup vs baseline: 1.3395x; 1.3395x over previous
#include <cuda_runtime.h>
#include <cuda_bf16.h>
#include <cstdint>

#define Bsz 64
#define Tsz 512
#define Isz 512
#define Hsz 512

// ---------------------------------------------------------------------------
// Static device scratch
// ---------------------------------------------------------------------------
__device__ float g_xproj[2u * Tsz * Bsz * Hsz];   // [d][t][b][h]

// 16 independent group counters, padded to 128B each (own L2 sector)
struct GCnt { unsigned v; unsigned pad[31]; };
__device__ GCnt g_gcount[16];

__global__ void reset_bar_kernel() {
    if (threadIdx.x < 16) g_gcount[threadIdx.x].v = 0;
}

// ---------------------------------------------------------------------------
// Packed fp32x2 helpers (Blackwell FFMA2 path)
// ---------------------------------------------------------------------------
typedef unsigned long long ull;

__device__ __forceinline__ ull ffma2(ull a, ull b, ull c) {
    ull d;
    asm("fma.rn.f32x2 %0, %1, %2, %3;" : "=l"(d) : "l"(a), "l"(b), "l"(c));
    return d;
}
__device__ __forceinline__ ull pack2(float x) {
    ull d;
    asm("mov.b64 %0, {%1, %1};" : "=l"(d) : "f"(x));
    return d;
}
__device__ __forceinline__ float2 unpack2(ull a) {
    float2 r;
    asm("mov.b64 {%0, %1}, %2;" : "=f"(r.x), "=f"(r.y) : "l"(a));
    return r;
}

// ---------------------------------------------------------------------------
// Phase 1: xproj = x @ Wx^T + b.  (unchanged — measured 641us, fma=67%)
// ---------------------------------------------------------------------------
__global__ void __launch_bounds__(256, 2) xproj_gemm_kernel(
    const float* __restrict__ x,
    const float* __restrict__ Wf, const float* __restrict__ bf,
    const float* __restrict__ Wb, const float* __restrict__ bb)
{
    const int d = blockIdx.z;
    const float* __restrict__ W    = d ? Wb : Wf;
    const float* __restrict__ bias = d ? bb : bf;

    const int mt = blockIdx.y << 7;
    const int b  = mt >> 9;
    const int t0 = mt & 511;
    const int n0 = blockIdx.x << 7;

    __shared__ float sA[8][132];
    __shared__ float sB[8][132];

    const int tid = threadIdx.x;
    const int r  = tid >> 1;
    const int cc = (tid & 1) * 4;

    const float* ap = x + ((size_t)(b * Tsz + t0 + r)) * Isz + cc;
    const float* bp = W + ((size_t)(n0 + r)) * Isz + cc;

    float4 ra = *(const float4*)ap;
    float4 rb = *(const float4*)bp;

    const int tr = tid >> 4;
    const int tc = tid & 15;

    ull acc2[8][4];
#pragma unroll
    for (int i = 0; i < 8; i++)
#pragma unroll
        for (int j = 0; j < 4; j++) acc2[i][j] = 0ull;

    for (int k0 = 0; k0 < Isz; k0 += 8) {
        __syncthreads();
        sA[cc + 0][r] = ra.x; sA[cc + 1][r] = ra.y;
        sA[cc + 2][r] = ra.z; sA[cc + 3][r] = ra.w;
        sB[cc + 0][r] = rb.x; sB[cc + 1][r] = rb.y;
        sB[cc + 2][r] = rb.z; sB[cc + 3][r] = rb.w;
        __syncthreads();

        if (k0 + 8 < Isz) {
            ra = *(const float4*)(ap + k0 + 8);
            rb = *(const float4*)(bp + k0 + 8);
        }

#pragma unroll
        for (int k = 0; k < 8; k++) {
            float4 a0 = *(const float4*)&sA[k][tr * 4];
            float4 a1 = *(const float4*)&sA[k][64 + tr * 4];
            ulonglong2 b0q = *(const ulonglong2*)&sB[k][tc * 4];
            ulonglong2 b1q = *(const ulonglong2*)&sB[k][64 + tc * 4];
            float am[8] = {a0.x, a0.y, a0.z, a0.w, a1.x, a1.y, a1.z, a1.w};
#pragma unroll
            for (int i = 0; i < 8; i++) {
                ull apk = pack2(am[i]);
                acc2[i][0] = ffma2(apk, b0q.x, acc2[i][0]);
                acc2[i][1] = ffma2(apk, b0q.y, acc2[i][1]);
                acc2[i][2] = ffma2(apk, b1q.x, acc2[i][2]);
                acc2[i][3] = ffma2(apk, b1q.y, acc2[i][3]);
            }
        }
    }

    float4 bias0 = *(const float4*)(bias + n0 + tc * 4);
    float4 bias1 = *(const float4*)(bias + n0 + 64 + tc * 4);

#pragma unroll
    for (int mi = 0; mi < 8; mi++) {
        int rloc = (mi < 4) ? (tr * 4 + mi) : (64 + tr * 4 + (mi - 4));
        int t = t0 + rloc;
        float* op = g_xproj + (((size_t)d * Tsz + t) * Bsz + b) * Hsz + n0;
        float2 p0 = unpack2(acc2[mi][0]);
        float2 p1 = unpack2(acc2[mi][1]);
        float2 p2 = unpack2(acc2[mi][2]);
        float2 p3 = unpack2(acc2[mi][3]);
        float4 o0, o1;
        o0.x = p0.x + bias0.x; o0.y = p0.y + bias0.y;
        o0.z = p1.x + bias0.z; o0.w = p1.y + bias0.w;
        o1.x = p2.x + bias1.x; o1.y = p2.y + bias1.y;
        o1.z = p3.x + bias1.z; o1.w = p3.y + bias1.w;
        *(float4*)(op + tc * 4)      = o0;
        *(float4*)(op + 64 + tc * 4) = o1;
    }
}

// ---------------------------------------------------------------------------
// Phase 2: persistent scan. 128 CTAs = (2 dir) x (8 btile) x (8 ctile).
// CTA owns 8 batches x 64 cols; W slice resident in smem; h exchanged via y
// in L2. Barrier: per-(dir,btile) group of 8 CTAs, monotonic counter.
//
// smem (floats):
//   WS[kc][k'][c]  kc<32, k'<16, c<64   chunk stride 1028 (odd 16B units)
//   HS[kc][b][kk]  kc<32, b<8,  kk<16   chunk stride 132  (odd 16B units)
// ---------------------------------------------------------------------------
#define SCAN_CTAS 128
#define WCH 1028
#define HCH 132

__global__ void __launch_bounds__(256) scan_kernel(
    const float* __restrict__ h0f, const float* __restrict__ h0b,
    const float* __restrict__ Whf, const float* __restrict__ Whb,
    float* __restrict__ y)
{
    extern __shared__ float sm[];
    float* WS = sm;               // 32 * 1028
    float* HS = sm + 32 * WCH;    // 32 * 132

    const int cta   = blockIdx.x;
    const int dir   = cta >> 6;
    const int btile = (cta >> 3) & 7;
    const int group = cta >> 3;     // 0..15 : (dir,btile)
    const int b0    = btile << 3;
    const int cbase = (cta & 7) << 6;

    const float* __restrict__ Wh = dir ? Whb : Whf;
    const float* __restrict__ h0 = dir ? h0b : h0f;

    const int tid = threadIdx.x;

    // ---- load W slice once, chunked k-major ----
    for (int i = tid; i < 64 * 128; i += 256) {
        int c  = i >> 7;
        int k4 = (i & 127) * 4;
        float4 v = *(const float4*)(Wh + (size_t)(cbase + c) * Hsz + k4);
        int kc = k4 >> 4, kk = k4 & 15;
        float* wsl = WS + kc * WCH + kk * 64 + c;
        wsl[0 * 64] = v.x; wsl[1 * 64] = v.y; wsl[2 * 64] = v.z; wsl[3 * 64] = v.w;
    }

    const int lane = tid & 31;
    const int w    = tid >> 5;
    const int kc   = lane;
    const int c0   = w << 3;

    // outputs of this lane after the halving butterfly (o = b_local*8 + c_local)
    const int o0 = ((lane & 1) << 5) | (((lane >> 1) & 1) << 4) |
                   (((lane >> 2) & 1) << 3) | (((lane >> 3) & 1) << 2) |
                   (((lane >> 4) & 1) << 1);
    const int b_out = b0 + (o0 >> 3);
    const int colg  = cbase + c0 + (o0 & 7);

    unsigned target = 0;
    volatile unsigned* vcnt = &g_gcount[group].v;

    for (int step = 0; step < Tsz; step++) {
        const int t = dir ? (Tsz - 1 - step) : step;

        // ---- stage h(t-1)[own 8 batches][:] into HS (16 KB) ----
        const float* src;
        size_t rstride;
        if (step == 0) {
            src = h0 + (size_t)b0 * Hsz; rstride = Hsz;
        } else {
            int tp = dir ? (t + 1) : (t - 1);
            src = y + ((size_t)b0 * Tsz + tp) * (2 * Hsz) + ((size_t)dir << 9);
            rstride = (size_t)Tsz * 2 * Hsz;
        }
        for (int i = tid; i < 1024; i += 256) {          // 8b x 128 float4
            int b  = i >> 7;
            int k  = (i & 127) * 4;
            float4 v = __ldcg((const float4*)(src + b * rstride + k));
            int kcx = k >> 4, kk = k & 15;
            *(float4*)&HS[kcx * HCH + b * 16 + kk] = v;
        }

        // xproj for this lane's outputs (barrier-independent, issue early)
        const float2 xp = __ldcg((const float2*)(
            g_xproj + (((size_t)dir * Tsz + t) * Bsz + b_out) * Hsz + colg));

        __syncthreads();

        // ---- 8b x 8c f32x2 tile over this lane's K-chunk of 16 ----
        ull acc[8][4];
#pragma unroll
        for (int b = 0; b < 8; b++)
#pragma unroll
            for (int j = 0; j < 4; j++) acc[b][j] = 0ull;

        const float* hp = HS + kc * HCH;
        const float* wp = WS + kc * WCH + c0;

#pragma unroll
        for (int kk4 = 0; kk4 < 16; kk4 += 4) {
            float4 hv[8];
#pragma unroll
            for (int b = 0; b < 8; b++)
                hv[b] = *(const float4*)(hp + b * 16 + kk4);
#pragma unroll
            for (int k2 = 0; k2 < 4; k2++) {
                const float* wrow = wp + (kk4 + k2) * 64;
                ulonglong2 wa = *(const ulonglong2*)(wrow);
                ulonglong2 wb = *(const ulonglong2*)(wrow + 4);
#pragma unroll
                for (int b = 0; b < 8; b++) {
                    float hs = (k2 == 0) ? hv[b].x : (k2 == 1) ? hv[b].y
                             : (k2 == 2) ? hv[b].z : hv[b].w;
                    ull hpk = pack2(hs);
                    acc[b][0] = ffma2(hpk, wa.x, acc[b][0]);
                    acc[b][1] = ffma2(hpk, wa.y, acc[b][1]);
                    acc[b][2] = ffma2(hpk, wb.x, acc[b][2]);
                    acc[b][3] = ffma2(hpk, wb.y, acc[b][3]);
                }
            }
        }

        // ---- unpack to 64 scalars (o = b*8 + c) ----
        float v[64];
#pragma unroll
        for (int b = 0; b < 8; b++)
#pragma unroll
            for (int cp = 0; cp < 4; cp++) {
                float2 u = unpack2(acc[b][cp]);
                v[b * 8 + cp * 2]     = u.x;
                v[b * 8 + cp * 2 + 1] = u.y;
            }

        // ---- 5-level jammed halving butterfly over the 32 kc lanes ----
        int n = 64;
#pragma unroll
        for (int m = 1; m < 32; m <<= 1) {
            n >>= 1;
            const bool hi = (lane & m) != 0;
#pragma unroll
            for (int i = 0; i < n; i++) {
                float send = hi ? v[i] : v[i + n];
                float keep = hi ? v[i + n] : v[i];
                v[i] = keep + __shfl_xor_sync(0xffffffffu, send, m);
            }
        }

        float r0 = tanhf(v[0] + xp.x);
        float r1 = tanhf(v[1] + xp.y);

        // streaming store of y (re-read only by the 8 group CTAs next step)
        float* yp = y + ((size_t)b_out * Tsz + t) * (2 * Hsz) + (dir << 9) + colg;
        __stcg((float2*)yp, make_float2(r0, r1));

        // ---- per-group barrier (8 CTAs, monotonic counter) ----
        __syncthreads();
        target += 8;
        if (tid == 0) {
            __threadfence();
            unsigned vv = atomicAdd((unsigned*)&g_gcount[group].v, 1u) + 1u;
            if (vv != target) {
                while (*vcnt < target) { }
            }
            __threadfence();
        }
        __syncthreads();
    }
}

// ---------------------------------------------------------------------------
// Tail: hT_f = hs_f[T-1], hT_b = hs_b[t=0]
// ---------------------------------------------------------------------------
__global__ void tail_kernel(float* __restrict__ out)
{
    const int b = blockIdx.x;
    const int k = threadIdx.x;
    const float* y = out;
    const size_t yN = (size_t)Bsz * Tsz * 2 * Hsz;
    out[yN + (size_t)b * Hsz + k] =
        y[((size_t)b * Tsz + (Tsz - 1)) * (2 * Hsz) + k];
    out[yN + (size_t)Bsz * Hsz + (size_t)b * Hsz + k] =
        y[((size_t)b * Tsz) * (2 * Hsz) + Hsz + k];
}

// ---------------------------------------------------------------------------
extern "C" void kernel_launch(void* const* d_in, const int* in_sizes, int n_in,
                              void* d_out, int out_size)
{
    const float* x     = (const float*)d_in[0];
    const float* h0f   = (const float*)d_in[1];
    const float* h0b   = (const float*)d_in[2];
    const float* Wxf_w = (const float*)d_in[3];
    const float* Wxf_b = (const float*)d_in[4];
    const float* Whf_w = (const float*)d_in[5];
    const float* Wxb_w = (const float*)d_in[6];
    const float* Wxb_b = (const float*)d_in[7];
    const float* Whb_w = (const float*)d_in[8];
    float* out = (float*)d_out;

    const int scan_smem = (32 * WCH + 32 * HCH) * (int)sizeof(float);
    cudaFuncSetAttribute(scan_kernel,
                         cudaFuncAttributeMaxDynamicSharedMemorySize, scan_smem);

    reset_bar_kernel<<<1, 32>>>();

    dim3 ggrid(4, 256, 2);
    xproj_gemm_kernel<<<ggrid, 256>>>(x, Wxf_w, Wxf_b, Wxb_w, Wxb_b);

    scan_kernel<<<SCAN_CTAS, 256, scan_smem>>>(h0f, h0b, Whf_w, Whb_w, out);

    tail_kernel<<<Bsz, Hsz>>>(out);
}

// round 9
// speedup vs baseline: 1.4120x; 1.0541x over previous
#include <cuda_runtime.h>
#include <cuda_bf16.h>
#include <cstdint>

#define Bsz 64
#define Tsz 512
#define Isz 512
#define Hsz 512

// ---------------------------------------------------------------------------
// Static device scratch
// ---------------------------------------------------------------------------
__device__ float g_xproj[2u * Tsz * Bsz * Hsz];   // [d][t][b][h]

// 16 independent chain counters (8 btile x 2 dir), padded to 128B each
struct GCnt { unsigned v; unsigned pad[31]; };
__device__ GCnt g_gcount[16];

__global__ void reset_bar_kernel() {
    if (threadIdx.x < 16) g_gcount[threadIdx.x].v = 0;
}

// ---------------------------------------------------------------------------
// Packed fp32x2 helpers (Blackwell FFMA2 path)
// ---------------------------------------------------------------------------
typedef unsigned long long ull;

__device__ __forceinline__ ull ffma2(ull a, ull b, ull c) {
    ull d;
    asm("fma.rn.f32x2 %0, %1, %2, %3;" : "=l"(d) : "l"(a), "l"(b), "l"(c));
    return d;
}
__device__ __forceinline__ ull pack2(float x) {
    ull d;
    asm("mov.b64 %0, {%1, %1};" : "=l"(d) : "f"(x));
    return d;
}
__device__ __forceinline__ float2 unpack2(ull a) {
    float2 r;
    asm("mov.b64 {%0, %1}, %2;" : "=f"(r.x), "=f"(r.y) : "l"(a));
    return r;
}

// ---------------------------------------------------------------------------
// Phase 1: xproj = x @ Wx^T + b.  (unchanged — measured 641us, fma=67%)
// ---------------------------------------------------------------------------
__global__ void __launch_bounds__(256, 2) xproj_gemm_kernel(
    const float* __restrict__ x,
    const float* __restrict__ Wf, const float* __restrict__ bf,
    const float* __restrict__ Wb, const float* __restrict__ bb)
{
    const int d = blockIdx.z;
    const float* __restrict__ W    = d ? Wb : Wf;
    const float* __restrict__ bias = d ? bb : bf;

    const int mt = blockIdx.y << 7;
    const int b  = mt >> 9;
    const int t0 = mt & 511;
    const int n0 = blockIdx.x << 7;

    __shared__ float sA[8][132];
    __shared__ float sB[8][132];

    const int tid = threadIdx.x;
    const int r  = tid >> 1;
    const int cc = (tid & 1) * 4;

    const float* ap = x + ((size_t)(b * Tsz + t0 + r)) * Isz + cc;
    const float* bp = W + ((size_t)(n0 + r)) * Isz + cc;

    float4 ra = *(const float4*)ap;
    float4 rb = *(const float4*)bp;

    const int tr = tid >> 4;
    const int tc = tid & 15;

    ull acc2[8][4];
#pragma unroll
    for (int i = 0; i < 8; i++)
#pragma unroll
        for (int j = 0; j < 4; j++) acc2[i][j] = 0ull;

    for (int k0 = 0; k0 < Isz; k0 += 8) {
        __syncthreads();
        sA[cc + 0][r] = ra.x; sA[cc + 1][r] = ra.y;
        sA[cc + 2][r] = ra.z; sA[cc + 3][r] = ra.w;
        sB[cc + 0][r] = rb.x; sB[cc + 1][r] = rb.y;
        sB[cc + 2][r] = rb.z; sB[cc + 3][r] = rb.w;
        __syncthreads();

        if (k0 + 8 < Isz) {
            ra = *(const float4*)(ap + k0 + 8);
            rb = *(const float4*)(bp + k0 + 8);
        }

#pragma unroll
        for (int k = 0; k < 8; k++) {
            float4 a0 = *(const float4*)&sA[k][tr * 4];
            float4 a1 = *(const float4*)&sA[k][64 + tr * 4];
            ulonglong2 b0q = *(const ulonglong2*)&sB[k][tc * 4];
            ulonglong2 b1q = *(const ulonglong2*)&sB[k][64 + tc * 4];
            float am[8] = {a0.x, a0.y, a0.z, a0.w, a1.x, a1.y, a1.z, a1.w};
#pragma unroll
            for (int i = 0; i < 8; i++) {
                ull apk = pack2(am[i]);
                acc2[i][0] = ffma2(apk, b0q.x, acc2[i][0]);
                acc2[i][1] = ffma2(apk, b0q.y, acc2[i][1]);
                acc2[i][2] = ffma2(apk, b1q.x, acc2[i][2]);
                acc2[i][3] = ffma2(apk, b1q.y, acc2[i][3]);
            }
        }
    }

    float4 bias0 = *(const float4*)(bias + n0 + tc * 4);
    float4 bias1 = *(const float4*)(bias + n0 + 64 + tc * 4);

#pragma unroll
    for (int mi = 0; mi < 8; mi++) {
        int rloc = (mi < 4) ? (tr * 4 + mi) : (64 + tr * 4 + (mi - 4));
        int t = t0 + rloc;
        float* op = g_xproj + (((size_t)d * Tsz + t) * Bsz + b) * Hsz + n0;
        float2 p0 = unpack2(acc2[mi][0]);
        float2 p1 = unpack2(acc2[mi][1]);
        float2 p2 = unpack2(acc2[mi][2]);
        float2 p3 = unpack2(acc2[mi][3]);
        float4 o0, o1;
        o0.x = p0.x + bias0.x; o0.y = p0.y + bias0.y;
        o0.z = p1.x + bias0.z; o0.w = p1.y + bias0.w;
        o1.x = p2.x + bias1.x; o1.y = p2.y + bias1.y;
        o1.z = p3.x + bias1.z; o1.w = p3.y + bias1.w;
        *(float4*)(op + tc * 4)      = o0;
        *(float4*)(op + 64 + tc * 4) = o1;
    }
}

// ---------------------------------------------------------------------------
// Phase 2: persistent scan, BOTH directions per CTA (warp-specialized).
// 128 CTAs = 8 btile x 16 ctile. CTA owns 8 batches x 32 cols x 2 dirs.
// Threads 0-127 (warps 0-3) = fwd chain; threads 128-255 (warps 4-7) = bwd.
// Each SMSP hosts 1 fwd + 1 bwd warp: one chain's sync/stage latency hides
// under the other chain's FFMA2 stream.
// Per-dir chain barrier: group = (btile,dir), 16 CTA arrivals, monotonic ctr.
//
// smem (floats):
//   WS[dir][kc][kk][c]  kc<32, kk<16, c<32  chunk stride 516 (129 16B-units)
//   HS[dir][kc][b][kk]  kc<32, b<8,  kk<16  chunk stride 132 (33 16B-units)
// ---------------------------------------------------------------------------
#define SCAN_CTAS 128
#define WSZ (32 * 516)
#define HSZ (32 * 132)

__global__ void __launch_bounds__(256) scan_kernel(
    const float* __restrict__ h0f, const float* __restrict__ h0b,
    const float* __restrict__ Whf, const float* __restrict__ Whb,
    float* __restrict__ y)
{
    extern __shared__ float sm[];

    const int cta   = blockIdx.x;
    const int btile = cta >> 4;
    const int ctile = cta & 15;
    const int b0    = btile << 3;   // 8 batches
    const int cbase = ctile << 5;   // 32 cols

    const int tid  = threadIdx.x;
    const int dir  = tid >> 7;      // 0 fwd (warps 0-3), 1 bwd (warps 4-7)
    const int htid = tid & 127;
    const int hw   = htid >> 5;     // warp within half, 0..3
    const int lane = tid & 31;
    const int gidx = (btile << 1) | dir;

    const float* __restrict__ Wh = dir ? Whb : Whf;
    const float* __restrict__ h0 = dir ? h0b : h0f;

    float* WS = sm + dir * WSZ;
    float* HS = sm + 2 * WSZ + dir * HSZ;

    // ---- load this dir's W slice once: WS[kc][kk][c] = Wh[cbase+c][kc*16+kk]
    for (int i = htid; i < 32 * 128; i += 128) {
        int c  = i >> 7;
        int k4 = (i & 127) * 4;
        float4 v = *(const float4*)(Wh + (size_t)(cbase + c) * Hsz + k4);
        int kc = k4 >> 4, kk = k4 & 15;
        float* p = WS + kc * 516 + kk * 32 + c;
        p[0] = v.x; p[32] = v.y; p[64] = v.z; p[96] = v.w;
    }
    __syncthreads();

    const int kc = lane;            // K-chunk of 16
    const int c0 = hw << 3;         // warp's 8 local cols

    // lane's 2 outputs after the halving butterfly (o = b_local*8 + c_local)
    const int o0 = ((lane & 1) << 5) | (((lane >> 1) & 1) << 4) |
                   (((lane >> 2) & 1) << 3) | (((lane >> 3) & 1) << 2) |
                   (((lane >> 4) & 1) << 1);
    const int b_out = b0 + (o0 >> 3);
    const int colg  = cbase + c0 + (o0 & 7);

    const float* hp = HS + kc * 132;
    const float* wp = WS + kc * 516 + c0;

    volatile unsigned* vcnt = &g_gcount[gidx].v;
    const int barid = 1 + dir;

    for (int step = 0; step < Tsz; step++) {
        const int t = dir ? (Tsz - 1 - step) : step;

        // xproj prefetch (chain-independent, in flight during the wait)
        const float2 xp = __ldcg((const float2*)(
            g_xproj + (((size_t)dir * Tsz + t) * Bsz + b_out) * Hsz + colg));

        // ---- wait for the 16 group CTAs to finish step-1 ----
        if (htid == 0 && step > 0) {
            unsigned tgt = (unsigned)(16 * step);
            while (*vcnt < tgt) { }
            __threadfence();
        }
        asm volatile("bar.sync %0, 128;" :: "r"(barid) : "memory");

        // ---- stage h(t-1)[own 8 batches][:] into HS (16 KB, 128 threads) ----
        const float* src;
        size_t rstride;
        if (step == 0) {
            src = h0 + (size_t)b0 * Hsz; rstride = Hsz;
        } else {
            int tp = dir ? (t + 1) : (t - 1);
            src = y + ((size_t)b0 * Tsz + tp) * (2 * Hsz) + ((size_t)dir << 9);
            rstride = (size_t)Tsz * 2 * Hsz;
        }
        for (int i = htid; i < 1024; i += 128) {       // 8b x 128 float4
            int b = i >> 7;
            int k = (i & 127) * 4;
            float4 v = __ldcg((const float4*)(src + b * rstride + k));
            *(float4*)&HS[(k >> 4) * 132 + b * 16 + (k & 15)] = v;
        }
        asm volatile("bar.sync %0, 128;" :: "r"(barid) : "memory");

        // ---- 8b x 8c f32x2 tile over this lane's K-chunk of 16 ----
        ull acc[8][4];
#pragma unroll
        for (int b = 0; b < 8; b++)
#pragma unroll
            for (int j = 0; j < 4; j++) acc[b][j] = 0ull;

#pragma unroll
        for (int kk4 = 0; kk4 < 16; kk4 += 4) {
            float4 hv[8];
#pragma unroll
            for (int b = 0; b < 8; b++)
                hv[b] = *(const float4*)(hp + b * 16 + kk4);
#pragma unroll
            for (int k2 = 0; k2 < 4; k2++) {
                const float* wrow = wp + (kk4 + k2) * 32;
                ulonglong2 wa = *(const ulonglong2*)(wrow);
                ulonglong2 wb = *(const ulonglong2*)(wrow + 4);
#pragma unroll
                for (int b = 0; b < 8; b++) {
                    float hs = (k2 == 0) ? hv[b].x : (k2 == 1) ? hv[b].y
                             : (k2 == 2) ? hv[b].z : hv[b].w;
                    ull hpk = pack2(hs);
                    acc[b][0] = ffma2(hpk, wa.x, acc[b][0]);
                    acc[b][1] = ffma2(hpk, wa.y, acc[b][1]);
                    acc[b][2] = ffma2(hpk, wb.x, acc[b][2]);
                    acc[b][3] = ffma2(hpk, wb.y, acc[b][3]);
                }
            }
        }

        // ---- unpack to 64 scalars (o = b*8 + c) ----
        float v[64];
#pragma unroll
        for (int b = 0; b < 8; b++)
#pragma unroll
            for (int cp = 0; cp < 4; cp++) {
                float2 u = unpack2(acc[b][cp]);
                v[b * 8 + cp * 2]     = u.x;
                v[b * 8 + cp * 2 + 1] = u.y;
            }

        // ---- 5-level jammed halving butterfly over the 32 kc lanes ----
        int n = 64;
#pragma unroll
        for (int m = 1; m < 32; m <<= 1) {
            n >>= 1;
            const bool hi = (lane & m) != 0;
#pragma unroll
            for (int i = 0; i < n; i++) {
                float send = hi ? v[i] : v[i + n];
                float keep = hi ? v[i + n] : v[i];
                v[i] = keep + __shfl_xor_sync(0xffffffffu, send, m);
            }
        }

        float r0 = tanhf(v[0] + xp.x);
        float r1 = tanhf(v[1] + xp.y);

        float* yp = y + ((size_t)b_out * Tsz + t) * (2 * Hsz) + (dir << 9) + colg;
        __stcg((float2*)yp, make_float2(r0, r1));

        // ---- order stores, then arrive on this chain's counter ----
        asm volatile("bar.sync %0, 128;" :: "r"(barid) : "memory");
        if (htid == 0) {
            __threadfence();
            atomicAdd((unsigned*)&g_gcount[gidx].v, 1u);
        }
    }
}

// ---------------------------------------------------------------------------
// Tail: hT_f = hs_f[T-1], hT_b = hs_b[t=0]
// ---------------------------------------------------------------------------
__global__ void tail_kernel(float* __restrict__ out)
{
    const int b = blockIdx.x;
    const int k = threadIdx.x;
    const float* y = out;
    const size_t yN = (size_t)Bsz * Tsz * 2 * Hsz;
    out[yN + (size_t)b * Hsz + k] =
        y[((size_t)b * Tsz + (Tsz - 1)) * (2 * Hsz) + k];
    out[yN + (size_t)Bsz * Hsz + (size_t)b * Hsz + k] =
        y[((size_t)b * Tsz) * (2 * Hsz) + Hsz + k];
}

// ---------------------------------------------------------------------------
extern "C" void kernel_launch(void* const* d_in, const int* in_sizes, int n_in,
                              void* d_out, int out_size)
{
    const float* x     = (const float*)d_in[0];
    const float* h0f   = (const float*)d_in[1];
    const float* h0b   = (const float*)d_in[2];
    const float* Wxf_w = (const float*)d_in[3];
    const float* Wxf_b = (const float*)d_in[4];
    const float* Whf_w = (const float*)d_in[5];
    const float* Wxb_w = (const float*)d_in[6];
    const float* Wxb_b = (const float*)d_in[7];
    const float* Whb_w = (const float*)d_in[8];
    float* out = (float*)d_out;

    const int scan_smem = (2 * WSZ + 2 * HSZ) * (int)sizeof(float);  // 165888 B
    cudaFuncSetAttribute(scan_kernel,
                         cudaFuncAttributeMaxDynamicSharedMemorySize, scan_smem);

    reset_bar_kernel<<<1, 32>>>();

    dim3 ggrid(4, 256, 2);
    xproj_gemm_kernel<<<ggrid, 256>>>(x, Wxf_w, Wxf_b, Wxb_w, Wxb_b);

    scan_kernel<<<SCAN_CTAS, 256, scan_smem>>>(h0f, h0b, Whf_w, Whb_w, out);

    tail_kernel<<<Bsz, Hsz>>>(out);
}

// round 10
// speedup vs baseline: 1.4248x; 1.0090x over previous
#include <cuda_runtime.h>
#include <cuda_bf16.h>
#include <cstdint>

#define Bsz 64
#define Tsz 512
#define Isz 512
#define Hsz 512

// ---------------------------------------------------------------------------
// Static device scratch
// ---------------------------------------------------------------------------
__device__ float g_xproj[2u * Tsz * Bsz * Hsz];   // [d][t][b][h]

// 16 independent chain counters (8 btile x 2 dir), padded to 128B each
struct GCnt { unsigned v; unsigned pad[31]; };
__device__ GCnt g_gcount[16];

__global__ void reset_bar_kernel() {
    if (threadIdx.x < 16) g_gcount[threadIdx.x].v = 0;
}

// ---------------------------------------------------------------------------
// Packed fp32x2 helpers (Blackwell FFMA2 path)
// ---------------------------------------------------------------------------
typedef unsigned long long ull;

__device__ __forceinline__ ull ffma2(ull a, ull b, ull c) {
    ull d;
    asm("fma.rn.f32x2 %0, %1, %2, %3;" : "=l"(d) : "l"(a), "l"(b), "l"(c));
    return d;
}
__device__ __forceinline__ ull pack2(float x) {
    ull d;
    asm("mov.b64 %0, {%1, %1};" : "=l"(d) : "f"(x));
    return d;
}
__device__ __forceinline__ float2 unpack2(ull a) {
    float2 r;
    asm("mov.b64 {%0, %1}, %2;" : "=f"(r.x), "=f"(r.y) : "l"(a));
    return r;
}

// ---------------------------------------------------------------------------
// Phase 1: xproj = x @ Wx^T + b.  (unchanged — measured 641us, fma=67%)
// ---------------------------------------------------------------------------
__global__ void __launch_bounds__(256, 2) xproj_gemm_kernel(
    const float* __restrict__ x,
    const float* __restrict__ Wf, const float* __restrict__ bf,
    const float* __restrict__ Wb, const float* __restrict__ bb)
{
    const int d = blockIdx.z;
    const float* __restrict__ W    = d ? Wb : Wf;
    const float* __restrict__ bias = d ? bb : bf;

    const int mt = blockIdx.y << 7;
    const int b  = mt >> 9;
    const int t0 = mt & 511;
    const int n0 = blockIdx.x << 7;

    __shared__ float sA[8][132];
    __shared__ float sB[8][132];

    const int tid = threadIdx.x;
    const int r  = tid >> 1;
    const int cc = (tid & 1) * 4;

    const float* ap = x + ((size_t)(b * Tsz + t0 + r)) * Isz + cc;
    const float* bp = W + ((size_t)(n0 + r)) * Isz + cc;

    float4 ra = *(const float4*)ap;
    float4 rb = *(const float4*)bp;

    const int tr = tid >> 4;
    const int tc = tid & 15;

    ull acc2[8][4];
#pragma unroll
    for (int i = 0; i < 8; i++)
#pragma unroll
        for (int j = 0; j < 4; j++) acc2[i][j] = 0ull;

    for (int k0 = 0; k0 < Isz; k0 += 8) {
        __syncthreads();
        sA[cc + 0][r] = ra.x; sA[cc + 1][r] = ra.y;
        sA[cc + 2][r] = ra.z; sA[cc + 3][r] = ra.w;
        sB[cc + 0][r] = rb.x; sB[cc + 1][r] = rb.y;
        sB[cc + 2][r] = rb.z; sB[cc + 3][r] = rb.w;
        __syncthreads();

        if (k0 + 8 < Isz) {
            ra = *(const float4*)(ap + k0 + 8);
            rb = *(const float4*)(bp + k0 + 8);
        }

#pragma unroll
        for (int k = 0; k < 8; k++) {
            float4 a0 = *(const float4*)&sA[k][tr * 4];
            float4 a1 = *(const float4*)&sA[k][64 + tr * 4];
            ulonglong2 b0q = *(const ulonglong2*)&sB[k][tc * 4];
            ulonglong2 b1q = *(const ulonglong2*)&sB[k][64 + tc * 4];
            float am[8] = {a0.x, a0.y, a0.z, a0.w, a1.x, a1.y, a1.z, a1.w};
#pragma unroll
            for (int i = 0; i < 8; i++) {
                ull apk = pack2(am[i]);
                acc2[i][0] = ffma2(apk, b0q.x, acc2[i][0]);
                acc2[i][1] = ffma2(apk, b0q.y, acc2[i][1]);
                acc2[i][2] = ffma2(apk, b1q.x, acc2[i][2]);
                acc2[i][3] = ffma2(apk, b1q.y, acc2[i][3]);
            }
        }
    }

    float4 bias0 = *(const float4*)(bias + n0 + tc * 4);
    float4 bias1 = *(const float4*)(bias + n0 + 64 + tc * 4);

#pragma unroll
    for (int mi = 0; mi < 8; mi++) {
        int rloc = (mi < 4) ? (tr * 4 + mi) : (64 + tr * 4 + (mi - 4));
        int t = t0 + rloc;
        float* op = g_xproj + (((size_t)d * Tsz + t) * Bsz + b) * Hsz + n0;
        float2 p0 = unpack2(acc2[mi][0]);
        float2 p1 = unpack2(acc2[mi][1]);
        float2 p2 = unpack2(acc2[mi][2]);
        float2 p3 = unpack2(acc2[mi][3]);
        float4 o0, o1;
        o0.x = p0.x + bias0.x; o0.y = p0.y + bias0.y;
        o0.z = p1.x + bias0.z; o0.w = p1.y + bias0.w;
        o1.x = p2.x + bias1.x; o1.y = p2.y + bias1.y;
        o1.z = p3.x + bias1.z; o1.w = p3.y + bias1.w;
        *(float4*)(op + tc * 4)      = o0;
        *(float4*)(op + 64 + tc * 4) = o1;
    }
}

// ---------------------------------------------------------------------------
// Phase 2: persistent scan, BOTH directions per CTA (warp-specialized),
// h consumed DIRECTLY from L2 (no smem staging, no stage barrier).
// 128 CTAs = 8 btile x 16 ctile. CTA owns 8 batches x 32 cols x 2 dirs.
// Threads 0-127 = fwd chain; 128-255 = bwd chain.
// Lane kc's K-subset: { q*128 + kc*4 + j : q<4, j<4 } -> for fixed (b,q) the
// warp's LDG.128 are contiguous (512B, 4 lines). W in smem permuted to match:
// WS[kc][q*4+j][c], chunk stride 516 floats (129 16B units, odd -> no bank
// conflicts). q-double-buffered h registers hide L2 latency.
// ---------------------------------------------------------------------------
#define SCAN_CTAS 128
#define WSZ (32 * 516)

__global__ void __launch_bounds__(256) scan_kernel(
    const float* __restrict__ h0f, const float* __restrict__ h0b,
    const float* __restrict__ Whf, const float* __restrict__ Whb,
    float* __restrict__ y)
{
    extern __shared__ float sm[];

    const int cta   = blockIdx.x;
    const int btile = cta >> 4;
    const int ctile = cta & 15;
    const int b0    = btile << 3;   // 8 batches
    const int cbase = ctile << 5;   // 32 cols

    const int tid  = threadIdx.x;
    const int dir  = tid >> 7;      // 0 fwd (warps 0-3), 1 bwd (warps 4-7)
    const int htid = tid & 127;
    const int hw   = htid >> 5;     // warp within half
    const int lane = tid & 31;
    const int gidx = (btile << 1) | dir;

    const float* __restrict__ Wh = dir ? Whb : Whf;
    const float* __restrict__ h0 = dir ? h0b : h0f;

    float* WS = sm + dir * WSZ;

    // ---- load this dir's W slice once, permuted to the lane K-subsets ----
    // WS[kc][q*4+j][c] = Wh[cbase+c][q*128 + kc*4 + j]
    for (int i = htid; i < 32 * 128; i += 128) {
        int c  = i >> 7;
        int k4 = (i & 127) * 4;                  // k4..k4+3
        float4 v = *(const float4*)(Wh + (size_t)(cbase + c) * Hsz + k4);
        int q  = k4 >> 7;
        int kc = (k4 & 127) >> 2;
        float* p = WS + kc * 516 + (q * 4) * 32 + c;
        p[0 * 32] = v.x; p[1 * 32] = v.y; p[2 * 32] = v.z; p[3 * 32] = v.w;
    }
    __syncthreads();

    const int kc = lane;
    const int c0 = hw << 3;         // warp's 8 local cols

    // lane's 2 outputs after the halving butterfly (o = b_local*8 + c_local)
    const int o0 = ((lane & 1) << 5) | (((lane >> 1) & 1) << 4) |
                   (((lane >> 2) & 1) << 3) | (((lane >> 3) & 1) << 2) |
                   (((lane >> 4) & 1) << 1);
    const int b_out = b0 + (o0 >> 3);
    const int colg  = cbase + c0 + (o0 & 7);

    const float* wp = WS + kc * 516 + c0;

    volatile unsigned* vcnt = &g_gcount[gidx].v;
    const int barid = 1 + dir;

    for (int step = 0; step < Tsz; step++) {
        const int t = dir ? (Tsz - 1 - step) : step;

        // xproj prefetch (chain-independent, in flight during the wait)
        const float2 xp = __ldcg((const float2*)(
            g_xproj + (((size_t)dir * Tsz + t) * Bsz + b_out) * Hsz + colg));

        // ---- wait for the 16 group CTAs to finish step-1 ----
        if (htid == 0 && step > 0) {
            unsigned tgt = (unsigned)(16 * step);
            while (*vcnt < tgt) { }
            __threadfence();
        }
        asm volatile("bar.sync %0, 128;" :: "r"(barid) : "memory");

        // ---- h source for this step (lane reads its own k-subset via L2) ----
        const float* hsrc;
        size_t rstride;
        if (step == 0) {
            hsrc = h0 + (size_t)b0 * Hsz; rstride = Hsz;
        } else {
            int tp = dir ? (t + 1) : (t - 1);
            hsrc = y + ((size_t)b0 * Tsz + tp) * (2 * Hsz) + ((size_t)dir << 9);
            rstride = (size_t)Tsz * 2 * Hsz;
        }
        const float* hbase = hsrc + (kc << 2);   // + q*128 + b*rstride

        ull acc[8][4];
#pragma unroll
        for (int b = 0; b < 8; b++)
#pragma unroll
            for (int j = 0; j < 4; j++) acc[b][j] = 0ull;

        // q-double-buffered direct loads
        float4 hq[8], hn[8];
#pragma unroll
        for (int b = 0; b < 8; b++)
            hq[b] = __ldcg((const float4*)(hbase + b * rstride));

#pragma unroll
        for (int q = 0; q < 4; q++) {
            if (q < 3) {
#pragma unroll
                for (int b = 0; b < 8; b++)
                    hn[b] = __ldcg((const float4*)(hbase + (q + 1) * 128 + b * rstride));
            }
#pragma unroll
            for (int j = 0; j < 4; j++) {
                const float* wrow = wp + (q * 4 + j) * 32;
                ulonglong2 wa = *(const ulonglong2*)(wrow);
                ulonglong2 wb = *(const ulonglong2*)(wrow + 4);
#pragma unroll
                for (int b = 0; b < 8; b++) {
                    float hs = (j == 0) ? hq[b].x : (j == 1) ? hq[b].y
                             : (j == 2) ? hq[b].z : hq[b].w;
                    ull hpk = pack2(hs);
                    acc[b][0] = ffma2(hpk, wa.x, acc[b][0]);
                    acc[b][1] = ffma2(hpk, wa.y, acc[b][1]);
                    acc[b][2] = ffma2(hpk, wb.x, acc[b][2]);
                    acc[b][3] = ffma2(hpk, wb.y, acc[b][3]);
                }
            }
            if (q < 3) {
#pragma unroll
                for (int b = 0; b < 8; b++) hq[b] = hn[b];
            }
        }

        // ---- unpack to 64 scalars (o = b*8 + c) ----
        float v[64];
#pragma unroll
        for (int b = 0; b < 8; b++)
#pragma unroll
            for (int cp = 0; cp < 4; cp++) {
                float2 u = unpack2(acc[b][cp]);
                v[b * 8 + cp * 2]     = u.x;
                v[b * 8 + cp * 2 + 1] = u.y;
            }

        // ---- 5-level jammed halving butterfly over the 32 kc lanes ----
        int n = 64;
#pragma unroll
        for (int m = 1; m < 32; m <<= 1) {
            n >>= 1;
            const bool hi = (lane & m) != 0;
#pragma unroll
            for (int i = 0; i < n; i++) {
                float send = hi ? v[i] : v[i + n];
                float keep = hi ? v[i + n] : v[i];
                v[i] = keep + __shfl_xor_sync(0xffffffffu, send, m);
            }
        }

        float r0 = tanhf(v[0] + xp.x);
        float r1 = tanhf(v[1] + xp.y);

        float* yp = y + ((size_t)b_out * Tsz + t) * (2 * Hsz) + (dir << 9) + colg;
        __stcg((float2*)yp, make_float2(r0, r1));

        // ---- order stores, then arrive on this chain's counter ----
        asm volatile("bar.sync %0, 128;" :: "r"(barid) : "memory");
        if (htid == 0) {
            __threadfence();
            atomicAdd((unsigned*)&g_gcount[gidx].v, 1u);
        }
    }
}

// ---------------------------------------------------------------------------
// Tail: hT_f = hs_f[T-1], hT_b = hs_b[t=0]
// ---------------------------------------------------------------------------
__global__ void tail_kernel(float* __restrict__ out)
{
    const int b = blockIdx.x;
    const int k = threadIdx.x;
    const float* y = out;
    const size_t yN = (size_t)Bsz * Tsz * 2 * Hsz;
    out[yN + (size_t)b * Hsz + k] =
        y[((size_t)b * Tsz + (Tsz - 1)) * (2 * Hsz) + k];
    out[yN + (size_t)Bsz * Hsz + (size_t)b * Hsz + k] =
        y[((size_t)b * Tsz) * (2 * Hsz) + Hsz + k];
}

// ---------------------------------------------------------------------------
extern "C" void kernel_launch(void* const* d_in, const int* in_sizes, int n_in,
                              void* d_out, int out_size)
{
    const float* x     = (const float*)d_in[0];
    const float* h0f   = (const float*)d_in[1];
    const float* h0b   = (const float*)d_in[2];
    const float* Wxf_w = (const float*)d_in[3];
    const float* Wxf_b = (const float*)d_in[4];
    const float* Whf_w = (const float*)d_in[5];
    const float* Wxb_w = (const float*)d_in[6];
    const float* Wxb_b = (const float*)d_in[7];
    const float* Whb_w = (const float*)d_in[8];
    float* out = (float*)d_out;

    const int scan_smem = (2 * WSZ) * (int)sizeof(float);  // 132096 B
    cudaFuncSetAttribute(scan_kernel,
                         cudaFuncAttributeMaxDynamicSharedMemorySize, scan_smem);

    reset_bar_kernel<<<1, 32>>>();

    dim3 ggrid(4, 256, 2);
    xproj_gemm_kernel<<<ggrid, 256>>>(x, Wxf_w, Wxf_b, Wxb_w, Wxb_b);

    scan_kernel<<<SCAN_CTAS, 256, scan_smem>>>(h0f, h0b, Whf_w, Whb_w, out);

    tail_kernel<<<Bsz, Hsz>>>(out);
}